// round 6
// baseline (speedup 1.0000x reference)
#include <cuda_runtime.h>
#include <cuda_bf16.h>
#include <cstdint>

typedef unsigned int u32;

// ============================================================================
// CustomLinear fused q/k/v — legacy tensor-core (mma.sync bf16 hi/lo split)
//   grid = (tokens/64, 8): blockIdx.y = packed GEMM g (2 heads x 64 feats)
//     g 0-1: Mq (region q, x2), g 2-3: Mk (k, x1), g 4-7: Mv (v, x1)
//   D[feat 0..127][tok 0..63] = W(hi/lo) @ X(hi/lo)^T, fp32 accum
//   Epilogue writes payload + zeros + scalar heads, exactly once per byte.
// ============================================================================

#define REGION 34078720L           // 8*4096*1040 floats per q/k/v region

// smem layout (bytes): XH 8K | XL 8K | WH 16K | WL 16K  = 49152 (static max)
#define OFF_XH 0
#define OFF_XL 8192
#define OFF_WH 16384
#define OFF_WL 32768

__device__ __forceinline__ u32 swz(u32 off) { return off ^ ((off >> 3) & 0x70); }

__device__ __forceinline__ void mma_bf16(float& c0, float& c1, float& c2, float& c3,
                                         u32 a0, u32 a1, u32 a2, u32 a3,
                                         u32 b0, u32 b1) {
    asm volatile(
        "mma.sync.aligned.m16n8k16.row.col.f32.bf16.bf16.f32 "
        "{%0,%1,%2,%3}, {%4,%5,%6,%7}, {%8,%9}, {%0,%1,%2,%3};"
        : "+f"(c0), "+f"(c1), "+f"(c2), "+f"(c3)
        : "r"(a0), "r"(a1), "r"(a2), "r"(a3), "r"(b0), "r"(b1));
}

__global__ void __launch_bounds__(256, 3) qkv_mma_kernel(
    const float* __restrict__ x,
    const float* __restrict__ Mq, const float* __restrict__ Bq,
    const float* __restrict__ Mk, const float* __restrict__ Bk,
    const float* __restrict__ Mv,
    float* __restrict__ out)
{
    __shared__ __align__(1024) char smem[49152];

    const int tid  = threadIdx.x;
    const int wid  = tid >> 5;
    const int lane = tid & 31;
    const int g_   = lane >> 2;          // fragment group id
    const int t4   = lane & 3;           // thread-in-group
    const long tok0 = (long)blockIdx.x * 64;

    const int g = blockIdx.y;                       // packed GEMM id
    const int r = (g < 2) ? 0 : (g < 4) ? 1 : 2;    // q / k / v
    const int p = (g < 2) ? g : (g < 4) ? g - 2 : g - 4;

    // ---- stage X slice (64 tok x 64 k) as bf16 hi/lo, swizzled ----
    const int soff = (r == 0) ? 65 : 0;             // q: x2, k/v: x1
    for (int idx = tid; idx < 64 * 64; idx += 256) {
        int t = idx >> 6, k = idx & 63;
        float v = __ldg(&x[(tok0 + t) * 130 + soff + k]);
        __nv_bfloat16 h = __float2bfloat16(v);
        __nv_bfloat16 l = __float2bfloat16(v - __bfloat162float(h));
        u32 off = swz((u32)(t * 128 + k * 2));
        *(__nv_bfloat16*)(smem + OFF_XH + off) = h;
        *(__nv_bfloat16*)(smem + OFF_XL + off) = l;
    }

    // ---- stage W (128 feat x 64 k) as bf16 hi/lo, swizzled ----
    const float* Mbase = (r == 0) ? Mq : (r == 1) ? Mk : Mv;
    for (int idx = tid; idx < 128 * 64; idx += 256) {
        int f = idx >> 6, k = idx & 63;
        int head = 2 * p + (f >> 6);
        float v = __ldg(&Mbase[head * 4096 + (f & 63) * 64 + k]);
        __nv_bfloat16 h = __float2bfloat16(v);
        __nv_bfloat16 l = __float2bfloat16(v - __bfloat162float(h));
        u32 off = swz((u32)(f * 128 + k * 2));
        *(__nv_bfloat16*)(smem + OFF_WH + off) = h;
        *(__nv_bfloat16*)(smem + OFF_WL + off) = l;
    }
    __syncthreads();

    // ---- main loop: warp = 16 feats (fb) x 64 tokens ----
    const int fb = wid * 16;
    const u32 XS = (u32)g_ << 4;         // per-thread swizzle XOR (row%8 == g_)

    float c[8][4];
    #pragma unroll
    for (int nt = 0; nt < 8; nt++)
        { c[nt][0] = 0.f; c[nt][1] = 0.f; c[nt][2] = 0.f; c[nt][3] = 0.f; }

    const u32 aoff0 = (u32)((fb + g_) * 128 + t4 * 4);
    const u32 boff0 = (u32)(g_ * 128 + t4 * 4);

    #pragma unroll
    for (int kt = 0; kt < 4; kt++) {
        const u32 ka = aoff0 + kt * 32;
        u32 ah0 = *(const u32*)(smem + OFF_WH + ((ka         ) ^ XS));
        u32 ah1 = *(const u32*)(smem + OFF_WH + ((ka + 1024  ) ^ XS));
        u32 ah2 = *(const u32*)(smem + OFF_WH + ((ka + 16    ) ^ XS));
        u32 ah3 = *(const u32*)(smem + OFF_WH + ((ka + 1040  ) ^ XS));
        u32 al0 = *(const u32*)(smem + OFF_WL + ((ka         ) ^ XS));
        u32 al1 = *(const u32*)(smem + OFF_WL + ((ka + 1024  ) ^ XS));
        u32 al2 = *(const u32*)(smem + OFF_WL + ((ka + 16    ) ^ XS));
        u32 al3 = *(const u32*)(smem + OFF_WL + ((ka + 1040  ) ^ XS));

        #pragma unroll
        for (int nt = 0; nt < 8; nt++) {
            const u32 kb = boff0 + nt * 1024 + kt * 32;
            u32 bh0 = *(const u32*)(smem + OFF_XH + ((kb     ) ^ XS));
            u32 bh1 = *(const u32*)(smem + OFF_XH + ((kb + 16) ^ XS));
            u32 bl0 = *(const u32*)(smem + OFF_XL + ((kb     ) ^ XS));
            u32 bl1 = *(const u32*)(smem + OFF_XL + ((kb + 16) ^ XS));
            mma_bf16(c[nt][0], c[nt][1], c[nt][2], c[nt][3],
                     ah0, ah1, ah2, ah3, bh0, bh1);
            mma_bf16(c[nt][0], c[nt][1], c[nt][2], c[nt][3],
                     ah0, ah1, ah2, ah3, bl0, bl1);
            mma_bf16(c[nt][0], c[nt][1], c[nt][2], c[nt][3],
                     al0, al1, al2, al3, bh0, bh1);
        }
    }

    // ---- epilogue: payload stores (fully-packed 32B sectors) ----
    float* rbase = out + (long)r * REGION;
    {
        const int head = 2 * p + (fb >> 6);
        const int fh   = (fb & 63) + g_;             // feat-in-head for c0/c1
        float* pbase = rbase + head * 130 + 65;
        #pragma unroll
        for (int nt = 0; nt < 8; nt++) {
            long t0 = tok0 + nt * 8 + 2 * t4;
            float* q0 = pbase + t0 * 1040 + fh;
            q0[0]        = c[nt][0];
            q0[1040]     = c[nt][1];
            q0[8]        = c[nt][2];
            q0[1048]     = c[nt][3];
        }
    }

    // ---- zeros + scalars: warp wid handles tokens [wid*8, wid*8+8) ----
    {
        const int h0 = 2 * p, h1 = 2 * p + 1, e0 = 4 + 2 * p;
        float tb0 = 0.f, tb1 = 0.f, ebA = 0.f, ebB = 0.f;
        if (r < 2) {
            const float* Bv = r ? Bk : Bq;
            tb0 = __ldg(Bv + h0);     tb1 = __ldg(Bv + h1);
            ebA = __ldg(Bv + 4 + 2 * p); ebB = __ldg(Bv + 5 + 2 * p);
        }
        const float2 z2 = make_float2(0.f, 0.f);
        #pragma unroll
        for (int tt = 0; tt < 8; tt++) {
            long tok = tok0 + wid * 8 + tt;
            float* ob = rbase + tok * 1040;

            ((float2*)(ob + h0 * 130))[lane] = z2;   // head h0 slots 0..63
            ((float2*)(ob + h1 * 130))[lane] = z2;   // head h1 slots 0..63

            if (lane == 0) {
                float sl = (r < 2) ? __ldg(&x[tok * 130 + 129]) : 0.f;
                ob[h0 * 130 + 64]  = 0.f;
                ob[h1 * 130 + 64]  = 0.f;
                ob[h0 * 130 + 129] = (r < 2) ? sl * tb0 : 0.f;
                ob[h1 * 130 + 129] = (r < 2) ? sl * tb1 : 0.f;
            }

            if (r < 2) {
                // scalar-only heads e0, e0+1: 130 zeros except slot 65
                ((float2*)(ob + e0 * 130))[lane]       = z2;   // 0..63
                ((float2*)(ob + (e0 + 1) * 130))[lane] = z2;
                float sv = 0.f;
                if (lane == 0) {
                    sv = (r == 0) ? __ldg(&x[tok * 130 + 129])
                                  : __ldg(&x[tok * 130 + 64]);
                }
                float2 vA = (lane == 0) ? make_float2(0.f, sv * ebA) : z2;
                float2 vB = (lane == 0) ? make_float2(0.f, sv * ebB) : z2;
                ((float2*)(ob + e0 * 130 + 64))[lane]       = vA;  // 64..127
                ((float2*)(ob + (e0 + 1) * 130 + 64))[lane] = vB;
                if (lane == 0) {
                    ((float2*)(ob + e0 * 130 + 128))[0]       = z2;  // 128,129
                    ((float2*)(ob + (e0 + 1) * 130 + 128))[0] = z2;
                }
            }
        }
    }
}

extern "C" void kernel_launch(void* const* d_in, const int* in_sizes, int n_in,
                              void* d_out, int out_size) {
    const float* x  = (const float*)d_in[0];
    const float* Mq = (const float*)d_in[1];
    const float* Bq = (const float*)d_in[2];
    const float* Mk = (const float*)d_in[3];
    const float* Bk = (const float*)d_in[4];
    const float* Mv = (const float*)d_in[5];
    float* out = (float*)d_out;

    const int tokens = in_sizes[0] / 130;   // 32768
    dim3 grid(tokens / 64, 8);
    qkv_mma_kernel<<<grid, 256>>>(x, Mq, Bq, Mk, Bk, Mv, out);
}